// round 9
// baseline (speedup 1.0000x reference)
#include <cuda_runtime.h>
#include <cuda_bf16.h>

#define TT 200
#define BB 1024
#define DD 128
#define NN 384        // 3 gates * 128
#define NCH 1600      // (TT*BB)/128 row-chunks
#define GCH 48        // chunk stride per gemm CTA (144 CTAs = 3 gates * 48)
#define XP 136        // padded k-length (bf16) for xproj smem tiles

// ---------------- device scratch (no runtime allocation allowed) ----------------
__device__ float g_Ax[(size_t)TT * BB * NN];                       // [row][n] row-major
__device__ __align__(16) __nv_bfloat16 g_Xhi[(size_t)TT * BB * DD];
__device__ __align__(16) __nv_bfloat16 g_Xlo[(size_t)TT * BB * DD];
__device__ __align__(16) __nv_bfloat16 g_Whi[3 * DD * DD];         // [gate][n][k]
__device__ __align__(16) __nv_bfloat16 g_Wlo[3 * DD * DD];

// ---------------- PTX helpers ----------------
static __device__ __forceinline__ void cp16(void* dst_sh, const void* src) {
    unsigned s = (unsigned)__cvta_generic_to_shared(dst_sh);
    asm volatile("cp.async.cg.shared.global [%0], [%1], 16;" :: "r"(s), "l"(src));
}
static __device__ __forceinline__ void cp_commit() { asm volatile("cp.async.commit_group;"); }
static __device__ __forceinline__ void cp_wait1() { asm volatile("cp.async.wait_group 1;"); }

// bf16 mma, fp32 accumulate, baseline PTX (compiles at compute_103)
static __device__ __forceinline__ void mma16816(float* d, const unsigned* a, const unsigned* b) {
    asm volatile(
        "mma.sync.aligned.m16n8k16.row.col.f32.bf16.bf16.f32 "
        "{%0,%1,%2,%3}, {%4,%5,%6,%7}, {%8,%9}, {%0,%1,%2,%3};"
        : "+f"(d[0]), "+f"(d[1]), "+f"(d[2]), "+f"(d[3])
        : "r"(a[0]), "r"(a[1]), "r"(a[2]), "r"(a[3]), "r"(b[0]), "r"(b[1]));
}

static __device__ __forceinline__ float fsig(float x) {
    return __fdividef(1.f, 1.f + __expf(-x));
}
static __device__ __forceinline__ float ftanh(float x) {
    float y = fminf(fmaxf(2.f * x, -30.f), 30.f);
    float e = __expf(y);
    return __fdividef(e - 1.f, e + 1.f);
}
static __device__ __forceinline__ unsigned pack2bf(__nv_bfloat16 a, __nv_bfloat16 b) {
    return (unsigned)__bfloat16_as_ushort(a) | ((unsigned)__bfloat16_as_ushort(b) << 16);
}

// k -> interleaved word index within a 64-word (128 bf16) row.
static __device__ __forceinline__ int word_of(int k) {
    int ks = k >> 4, r16 = k & 15;
    return ks * 8 + (((r16 & 7) >> 1) << 1) + (r16 >> 3);
}

// ==================== prep: X -> bf16 hi/lo (row-major) ====================
__global__ void prep_x(const float4* __restrict__ X4) {
    const size_t n4 = (size_t)TT * BB * DD / 4;
    for (size_t i = (size_t)blockIdx.x * blockDim.x + threadIdx.x; i < n4;
         i += (size_t)gridDim.x * blockDim.x) {
        float4 v = X4[i];
        __nv_bfloat16 hx = __float2bfloat16(v.x), hy = __float2bfloat16(v.y);
        __nv_bfloat16 hz = __float2bfloat16(v.z), hw = __float2bfloat16(v.w);
        uint2 h, l;
        h.x = pack2bf(hx, hy);
        h.y = pack2bf(hz, hw);
        l.x = pack2bf(__float2bfloat16(v.x - __bfloat162float(hx)),
                      __float2bfloat16(v.y - __bfloat162float(hy)));
        l.y = pack2bf(__float2bfloat16(v.z - __bfloat162float(hz)),
                      __float2bfloat16(v.w - __bfloat162float(hw)));
        ((uint2*)g_Xhi)[i] = h;
        ((uint2*)g_Xlo)[i] = l;
    }
}

// ==================== prep: Wa -> transposed [n][k] bf16 hi/lo ====================
__global__ void prep_w(const float* __restrict__ Wau, const float* __restrict__ War,
                       const float* __restrict__ Wac) {
    const int g = blockIdx.x;
    const float* W = (g == 0) ? Wau : ((g == 1) ? War : Wac);
    for (int idx = threadIdx.x; idx < DD * DD; idx += blockDim.x) {
        int n = idx >> 7, k = idx & 127;
        float v = W[k * DD + n];
        __nv_bfloat16 hi = __float2bfloat16(v);
        g_Whi[g * DD * DD + idx] = hi;
        g_Wlo[g * DD * DD + idx] = __float2bfloat16(v - __bfloat162float(hi));
    }
}

// ==================== phase 1 GEMM (mma.sync bf16, split-3): g_Ax = X @ Wg ====================
#define XTC_SMEM (6 * DD * XP * 2)   // 208896 bytes

static __device__ __forceinline__ void stageX(__nv_bfloat16* dst, int c, int tid) {
#pragma unroll
    for (int q = 0; q < 16; q++) {
        int id = q * 256 + tid;
        int sp = id >> 11, rr = (id >> 4) & 127, sg = id & 15;
        const __nv_bfloat16* src = (sp ? g_Xlo : g_Xhi) + (size_t)c * (DD * DD) + rr * DD + sg * 8;
        cp16(dst + sp * (DD * XP) + rr * XP + sg * 8, src);
    }
}

__global__ __launch_bounds__(256, 1) void xproj_tc() {
    extern __shared__ __align__(16) __nv_bfloat16 smp[];
    __nv_bfloat16* Xb0 = smp;
    __nv_bfloat16* Xb1 = smp + 2 * DD * XP;
    __nv_bfloat16* Wp  = smp + 4 * DD * XP;

    const int tid = threadIdx.x;
    const int gate = blockIdx.x / GCH;
    const int part = blockIdx.x % GCH;
    const int wid = tid >> 5, lane = tid & 31;
    const int g = lane >> 2, tg = lane & 3;
    const int wm = wid >> 2, wn = wid & 3;

#pragma unroll
    for (int q = 0; q < 16; q++) {
        int id = q * 256 + tid;
        int sp = id >> 11, rr = (id >> 4) & 127, sg = id & 15;
        const __nv_bfloat16* src = (sp ? g_Wlo : g_Whi) + gate * DD * DD + rr * DD + sg * 8;
        cp16(Wp + sp * (DD * XP) + rr * XP + sg * 8, src);
    }
    stageX(Xb0, part, tid);
    cp_commit();

    int buf = 0;
    for (int c = part; c < NCH; c += GCH) {
        const int cn = c + GCH;
        if (cn < NCH) stageX(buf ? Xb0 : Xb1, cn, tid);
        cp_commit();
        cp_wait1();
        __syncthreads();

        const __nv_bfloat16* Xhi_s = buf ? Xb1 : Xb0;
        const __nv_bfloat16* Xlo_s = Xhi_s + DD * XP;
        const __nv_bfloat16* Whi_s = Wp;
        const __nv_bfloat16* Wlo_s = Wp + DD * XP;

        float acc[4][4][4];
#pragma unroll
        for (int mt = 0; mt < 4; mt++)
#pragma unroll
            for (int nt = 0; nt < 4; nt++)
#pragma unroll
                for (int q = 0; q < 4; q++) acc[mt][nt][q] = 0.f;

        const int arow = wm * 64 + g;
        const int bcol = wn * 32 + g;

#pragma unroll
        for (int ks = 0; ks < 8; ks++) {
            const int k0 = ks * 16 + 2 * tg;
            unsigned ah[4][4], bh[4][2];
#pragma unroll
            for (int mt = 0; mt < 4; mt++) {
                const __nv_bfloat16* pa = Xhi_s + (arow + mt * 16) * XP + k0;
                ah[mt][0] = *(const unsigned*)pa;
                ah[mt][1] = *(const unsigned*)(pa + 8 * XP);
                ah[mt][2] = *(const unsigned*)(pa + 8);
                ah[mt][3] = *(const unsigned*)(pa + 8 * XP + 8);
            }
#pragma unroll
            for (int nt = 0; nt < 4; nt++) {
                const __nv_bfloat16* pb = Whi_s + (bcol + nt * 8) * XP + k0;
                bh[nt][0] = *(const unsigned*)pb;
                bh[nt][1] = *(const unsigned*)(pb + 8);
            }
#pragma unroll
            for (int mt = 0; mt < 4; mt++)
#pragma unroll
                for (int nt = 0; nt < 4; nt++) mma16816(acc[mt][nt], ah[mt], bh[nt]);
            {
                unsigned al[4][4];
#pragma unroll
                for (int mt = 0; mt < 4; mt++) {
                    const __nv_bfloat16* pa = Xlo_s + (arow + mt * 16) * XP + k0;
                    al[mt][0] = *(const unsigned*)pa;
                    al[mt][1] = *(const unsigned*)(pa + 8 * XP);
                    al[mt][2] = *(const unsigned*)(pa + 8);
                    al[mt][3] = *(const unsigned*)(pa + 8 * XP + 8);
                }
#pragma unroll
                for (int mt = 0; mt < 4; mt++)
#pragma unroll
                    for (int nt = 0; nt < 4; nt++) mma16816(acc[mt][nt], al[mt], bh[nt]);
            }
            {
                unsigned bl[4][2];
#pragma unroll
                for (int nt = 0; nt < 4; nt++) {
                    const __nv_bfloat16* pb = Wlo_s + (bcol + nt * 8) * XP + k0;
                    bl[nt][0] = *(const unsigned*)pb;
                    bl[nt][1] = *(const unsigned*)(pb + 8);
                }
#pragma unroll
                for (int mt = 0; mt < 4; mt++)
#pragma unroll
                    for (int nt = 0; nt < 4; nt++) mma16816(acc[mt][nt], ah[mt], bl[nt]);
            }
        }

        const size_t rbase = (size_t)c * 128;
#pragma unroll
        for (int mt = 0; mt < 4; mt++) {
#pragma unroll
            for (int nt = 0; nt < 4; nt++) {
                size_t r1 = rbase + wm * 64 + mt * 16 + g;
                int col = gate * 128 + wn * 32 + nt * 8 + 2 * tg;
                *(float2*)&g_Ax[r1 * NN + col] = make_float2(acc[mt][nt][0], acc[mt][nt][1]);
                *(float2*)&g_Ax[(r1 + 8) * NN + col] = make_float2(acc[mt][nt][2], acc[mt][nt][3]);
            }
        }
        __syncthreads();
        buf ^= 1;
    }
}

// ==================== phase 2: recurrence on mma.sync, 768 threads / 24 warps ====================
// 128 CTAs x 8 batch rows. Warp w owns n-tiles {16w, 16w+8} (all 3 split-products).
// B_hi of tile0 in registers; tile1 B_hi + both B_lo via LDS.
#define OFF_WLO 98304
#define OFF_SA  196608
#define OFF_SF  204800
#define OFF_PRE 209024
#define RC_SMEM 221568

__global__ __launch_bounds__(768, 1)
void recur_tc(const float* __restrict__ state0,
              const float* __restrict__ att,    // [T,B,1]
              const float* __restrict__ mask,   // [B,T]
              const float* __restrict__ bau, const float* __restrict__ bar,
              const float* __restrict__ bac,
              const float* __restrict__ Wbu, const float* __restrict__ Wbr,
              const float* __restrict__ Wbc,
              float* __restrict__ out) {
    extern __shared__ char sm[];
    unsigned* Whi = (unsigned*)sm;
    unsigned* Wlo = (unsigned*)(sm + OFF_WLO);
    unsigned* sA  = (unsigned*)(sm + OFF_SA);     // [split][16 rows][64 words]
    float* sf  = (float*)(sm + OFF_SF);           // [8][132] canonical fp32 state
    float* pre = (float*)(sm + OFF_PRE);          // [8][392] matvec results

    const int tid = threadIdx.x;
    const int lane = tid & 31, wid = tid >> 5;
    const int b0 = blockIdx.x * 8;
    const int d = tid & 127;
    const int r0 = (tid >> 7) & 3;       // update rows r0, r0+4 (tid<512 only)
    const int ar = lane >> 2;            // 0..7
    const int q2 = (lane & 3) * 2;
    const int bn0 = (wid << 4) + ar;     // tile0 B-row; tile1 = bn0 + 8

    // ---- init resident W (hi/lo, interleaved + rotated) ----
#pragma unroll 4
    for (int i = 0; i < 64; i++) {
        int idx = i * 768 + tid;         // 0..49151
        int g = idx >> 14;
        int k = (idx >> 7) & 127;
        int dd = idx & 127;
        const float* Wg = (g == 0) ? Wbu : ((g == 1) ? Wbr : Wbc);
        float v = Wg[k * DD + dd];
        __nv_bfloat16 h = __float2bfloat16(v);
        __nv_bfloat16 l = __float2bfloat16(v - __bfloat162float(h));
        int n = g * 128 + dd;
        int pos = n * 64 + ((word_of(k) + 8 * (n & 7)) & 63);
        ((__nv_bfloat16*)Whi)[pos * 2 + (k & 1)] = h;
        ((__nv_bfloat16*)Wlo)[pos * 2 + (k & 1)] = l;
    }
    // zero sA rows 8..15 (both splits)
    for (int i = tid; i < 2 * 8 * 64; i += 768) {
        int sp = i >> 9, rw = i & 511;
        sA[sp * 1024 + (8 + (rw >> 6)) * 64 + (rw & 63)] = 0;
    }
    // load initial state (fp32 canonical + hi/lo splits): rows r0, r0+4 (tid<512)
    float bu = bau[d], brg = bar[d], bcg = bac[d];
    if (tid < 512) {
#pragma unroll
        for (int jj = 0; jj < 2; jj++) {
            int r = r0 + 4 * jj;
            float v = state0[(size_t)(b0 + r) * DD + d];
            sf[r * 132 + d] = v;
            __nv_bfloat16 h = __float2bfloat16(v);
            __nv_bfloat16 l = __float2bfloat16(v - __bfloat162float(h));
            int pos = r * 64 + ((word_of(d) + 8 * r) & 63);
            ((__nv_bfloat16*)sA)[pos * 2 + (d & 1)] = h;
            ((__nv_bfloat16*)sA)[2048 + pos * 2 + (d & 1)] = l;
        }
    }
    __syncthreads();

    // ---- preload tile0 B_hi fragments into registers (step-invariant) ----
    unsigned bhr[8][2];
#pragma unroll
    for (int ks = 0; ks < 8; ks++) {
        const int rot = (ks * 8 + q2 + 8 * ar) & 63;
        uint2 BH = *(const uint2*)(Whi + bn0 * 64 + rot);
        bhr[ks][0] = BH.x;
        bhr[ks][1] = BH.y;
    }

    for (int t = 0; t < TT; t++) {
        // early LDG: this step's x-projections + att/mask (update threads only)
        float axu[2], axr[2], axc[2], av[2], mv[2];
        if (tid < 512) {
#pragma unroll
            for (int jj = 0; jj < 2; jj++) {
                int r = r0 + 4 * jj;
                size_t row = (size_t)t * BB + b0 + r;
                axu[jj] = g_Ax[row * NN + d];
                axr[jj] = g_Ax[row * NN + 128 + d];
                axc[jj] = g_Ax[row * NN + 256 + d];
                av[jj] = att[t * BB + b0 + r];
                mv[jj] = mask[(size_t)(b0 + r) * TT + t];
            }
        }

        // ---- matvec: s @ Wb, 3-product split-bf16, 2 tiles per warp ----
        float accA[2][4], accB[2][4];
#pragma unroll
        for (int i = 0; i < 2; i++)
#pragma unroll
            for (int q = 0; q < 4; q++) { accA[i][q] = 0.f; accB[i][q] = 0.f; }

#pragma unroll
        for (int ks = 0; ks < 8; ks++) {
            const int rot = (ks * 8 + q2 + 8 * ar) & 63;
            uint2 AH0 = *(const uint2*)(sA + (ar * 64 + rot));
            uint2 AH1 = *(const uint2*)(sA + ((ar + 8) * 64 + rot));
            uint2 AL0 = *(const uint2*)(sA + 1024 + (ar * 64 + rot));
            uint2 AL1 = *(const uint2*)(sA + 1024 + ((ar + 8) * 64 + rot));
            unsigned ah[4] = {AH0.x, AH1.x, AH0.y, AH1.y};
            unsigned al[4] = {AL0.x, AL1.x, AL0.y, AL1.y};
            // tile 0: B_hi from regs, B_lo from smem
            {
                uint2 BL = *(const uint2*)(Wlo + bn0 * 64 + rot);
                unsigned bl[2] = {BL.x, BL.y};
                mma16816(accA[0], ah, bhr[ks]);
                mma16816(accB[0], al, bhr[ks]);
                mma16816(accB[0], ah, bl);
            }
            // tile 1: B_hi + B_lo from smem
            {
                uint2 BH = *(const uint2*)(Whi + (bn0 + 8) * 64 + rot);
                uint2 BL = *(const uint2*)(Wlo + (bn0 + 8) * 64 + rot);
                unsigned bh[2] = {BH.x, BH.y};
                unsigned bl[2] = {BL.x, BL.y};
                mma16816(accA[1], ah, bh);
                mma16816(accB[1], al, bh);
                mma16816(accB[1], ah, bl);
            }
        }

        // store row ar, cols 16*wid + 8*i + q2
#pragma unroll
        for (int i = 0; i < 2; i++) {
            int col = (wid << 4) + 8 * i + q2;
            *(float2*)(pre + ar * 392 + col) =
                make_float2(accA[i][0] + accB[i][0], accA[i][1] + accB[i][1]);
        }
        __syncthreads();   // B1: pre visible; sA reads done

        // ---- gates + state update (tid<512: rows r0, r0+4; same d) ----
        if (tid < 512) {
#pragma unroll
            for (int jj = 0; jj < 2; jj++) {
                int r = r0 + 4 * jj;
                float pu = pre[r * 392 + d];
                float pr = pre[r * 392 + 128 + d];
                float pc = pre[r * 392 + 256 + d];
                float u = fsig(axu[jj] + bu + pu);
                float rg = fsig(axr[jj] + brg + pr);
                float c = ftanh(axc[jj] + bcg + rg * pc);
                float so = sf[r * 132 + d];
                float sn = so + mv[jj] * (av[jj] * u * (c - so));
                sf[r * 132 + d] = sn;
                __nv_bfloat16 h = __float2bfloat16(sn);
                __nv_bfloat16 l = __float2bfloat16(sn - __bfloat162float(h));
                int pos = r * 64 + ((word_of(d) + 8 * r) & 63);
                ((__nv_bfloat16*)sA)[pos * 2 + (d & 1)] = h;
                ((__nv_bfloat16*)sA)[2048 + pos * 2 + (d & 1)] = l;
            }
        }
        __syncthreads();   // B2: new state visible for next matvec
    }

    if (tid < 512) {
#pragma unroll
        for (int jj = 0; jj < 2; jj++) {
            int r = r0 + 4 * jj;
            out[(size_t)(b0 + r) * DD + d] = sf[r * 132 + d];
        }
    }
}

// ---------------- launch ----------------
extern "C" void kernel_launch(void* const* d_in, const int* in_sizes, int n_in,
                              void* d_out, int out_size) {
    const float* inputs = (const float*)d_in[0];   // [T,B,D]
    const float* state  = (const float*)d_in[1];   // [B,D]
    const float* att    = (const float*)d_in[2];   // [T,B,1]
    const float* mask   = (const float*)d_in[3];   // [B,T]
    // d_in[4] = max_len (compile-time TT)
    const float* Wau = (const float*)d_in[5];
    const float* bau = (const float*)d_in[6];
    const float* Wbu = (const float*)d_in[7];
    const float* War = (const float*)d_in[8];
    const float* bar = (const float*)d_in[9];
    const float* Wbr = (const float*)d_in[10];
    const float* Wac = (const float*)d_in[11];
    const float* bac = (const float*)d_in[12];
    const float* Wbc = (const float*)d_in[13];

    cudaFuncSetAttribute(xproj_tc, cudaFuncAttributeMaxDynamicSharedMemorySize, XTC_SMEM);
    cudaFuncSetAttribute(recur_tc, cudaFuncAttributeMaxDynamicSharedMemorySize, RC_SMEM);

    prep_w<<<3, 256>>>(Wau, War, Wac);
    prep_x<<<2048, 256>>>((const float4*)inputs);
    xproj_tc<<<3 * GCH, 256, XTC_SMEM>>>();
    recur_tc<<<BB / 8, 768, RC_SMEM>>>(state, att, mask, bau, bar, bac,
                                       Wbu, Wbr, Wbc, (float*)d_out);
}

// round 10
// speedup vs baseline: 1.4863x; 1.4863x over previous
#include <cuda_runtime.h>
#include <cuda_bf16.h>

#define TT 200
#define BB 1024
#define DD 128
#define NN 384        // 3 gates * 128
#define NCH 1600      // (TT*BB)/128 row-chunks
#define GCH 48        // chunk stride per gemm CTA (144 CTAs = 3 gates * 48)
#define XP 136        // padded k-length (bf16) for xproj smem tiles

// ---------------- device scratch (no runtime allocation allowed) ----------------
__device__ float g_Ax[(size_t)TT * BB * NN];                       // [row][n] row-major
__device__ __align__(16) __nv_bfloat16 g_Xhi[(size_t)TT * BB * DD];
__device__ __align__(16) __nv_bfloat16 g_Xlo[(size_t)TT * BB * DD];
__device__ __align__(16) __nv_bfloat16 g_Whi[3 * DD * DD];         // [gate][n][k]
__device__ __align__(16) __nv_bfloat16 g_Wlo[3 * DD * DD];

// ---------------- PTX helpers ----------------
static __device__ __forceinline__ void cp16(void* dst_sh, const void* src) {
    unsigned s = (unsigned)__cvta_generic_to_shared(dst_sh);
    asm volatile("cp.async.cg.shared.global [%0], [%1], 16;" :: "r"(s), "l"(src));
}
static __device__ __forceinline__ void cp_commit() { asm volatile("cp.async.commit_group;"); }
static __device__ __forceinline__ void cp_wait1() { asm volatile("cp.async.wait_group 1;"); }

// bf16 mma, fp32 accumulate, baseline PTX (compiles at compute_103)
static __device__ __forceinline__ void mma16816(float* d, const unsigned* a, const unsigned* b) {
    asm volatile(
        "mma.sync.aligned.m16n8k16.row.col.f32.bf16.bf16.f32 "
        "{%0,%1,%2,%3}, {%4,%5,%6,%7}, {%8,%9}, {%0,%1,%2,%3};"
        : "+f"(d[0]), "+f"(d[1]), "+f"(d[2]), "+f"(d[3])
        : "r"(a[0]), "r"(a[1]), "r"(a[2]), "r"(a[3]), "r"(b[0]), "r"(b[1]));
}

static __device__ __forceinline__ float fsig(float x) {
    return __fdividef(1.f, 1.f + __expf(-x));
}
static __device__ __forceinline__ float ftanh(float x) {
    float y = fminf(fmaxf(2.f * x, -30.f), 30.f);
    float e = __expf(y);
    return __fdividef(e - 1.f, e + 1.f);
}
static __device__ __forceinline__ unsigned pack2bf(__nv_bfloat16 a, __nv_bfloat16 b) {
    return (unsigned)__bfloat16_as_ushort(a) | ((unsigned)__bfloat16_as_ushort(b) << 16);
}

// k -> interleaved word index within a 64-word (128 bf16) row.
static __device__ __forceinline__ int word_of(int k) {
    int ks = k >> 4, r16 = k & 15;
    return ks * 8 + (((r16 & 7) >> 1) << 1) + (r16 >> 3);
}

// ==================== prep: X -> bf16 hi/lo (row-major) ====================
__global__ void prep_x(const float4* __restrict__ X4) {
    const size_t n4 = (size_t)TT * BB * DD / 4;
    for (size_t i = (size_t)blockIdx.x * blockDim.x + threadIdx.x; i < n4;
         i += (size_t)gridDim.x * blockDim.x) {
        float4 v = X4[i];
        __nv_bfloat16 hx = __float2bfloat16(v.x), hy = __float2bfloat16(v.y);
        __nv_bfloat16 hz = __float2bfloat16(v.z), hw = __float2bfloat16(v.w);
        uint2 h, l;
        h.x = pack2bf(hx, hy);
        h.y = pack2bf(hz, hw);
        l.x = pack2bf(__float2bfloat16(v.x - __bfloat162float(hx)),
                      __float2bfloat16(v.y - __bfloat162float(hy)));
        l.y = pack2bf(__float2bfloat16(v.z - __bfloat162float(hz)),
                      __float2bfloat16(v.w - __bfloat162float(hw)));
        ((uint2*)g_Xhi)[i] = h;
        ((uint2*)g_Xlo)[i] = l;
    }
}

// ==================== prep: Wa -> transposed [n][k] bf16 hi/lo ====================
__global__ void prep_w(const float* __restrict__ Wau, const float* __restrict__ War,
                       const float* __restrict__ Wac) {
    const int g = blockIdx.x;
    const float* W = (g == 0) ? Wau : ((g == 1) ? War : Wac);
    for (int idx = threadIdx.x; idx < DD * DD; idx += blockDim.x) {
        int n = idx >> 7, k = idx & 127;
        float v = W[k * DD + n];
        __nv_bfloat16 hi = __float2bfloat16(v);
        g_Whi[g * DD * DD + idx] = hi;
        g_Wlo[g * DD * DD + idx] = __float2bfloat16(v - __bfloat162float(hi));
    }
}

// ==================== phase 1 GEMM (mma.sync bf16, split-3): g_Ax = X @ Wg ====================
#define XTC_SMEM (6 * DD * XP * 2)   // 208896 bytes

static __device__ __forceinline__ void stageX(__nv_bfloat16* dst, int c, int tid) {
#pragma unroll
    for (int q = 0; q < 16; q++) {
        int id = q * 256 + tid;
        int sp = id >> 11, rr = (id >> 4) & 127, sg = id & 15;
        const __nv_bfloat16* src = (sp ? g_Xlo : g_Xhi) + (size_t)c * (DD * DD) + rr * DD + sg * 8;
        cp16(dst + sp * (DD * XP) + rr * XP + sg * 8, src);
    }
}

__global__ __launch_bounds__(256, 1) void xproj_tc() {
    extern __shared__ __align__(16) __nv_bfloat16 smp[];
    __nv_bfloat16* Xb0 = smp;
    __nv_bfloat16* Xb1 = smp + 2 * DD * XP;
    __nv_bfloat16* Wp  = smp + 4 * DD * XP;

    const int tid = threadIdx.x;
    const int gate = blockIdx.x / GCH;
    const int part = blockIdx.x % GCH;
    const int wid = tid >> 5, lane = tid & 31;
    const int g = lane >> 2, tg = lane & 3;
    const int wm = wid >> 2, wn = wid & 3;

#pragma unroll
    for (int q = 0; q < 16; q++) {
        int id = q * 256 + tid;
        int sp = id >> 11, rr = (id >> 4) & 127, sg = id & 15;
        const __nv_bfloat16* src = (sp ? g_Wlo : g_Whi) + gate * DD * DD + rr * DD + sg * 8;
        cp16(Wp + sp * (DD * XP) + rr * XP + sg * 8, src);
    }
    stageX(Xb0, part, tid);
    cp_commit();

    int buf = 0;
    for (int c = part; c < NCH; c += GCH) {
        const int cn = c + GCH;
        if (cn < NCH) stageX(buf ? Xb0 : Xb1, cn, tid);
        cp_commit();
        cp_wait1();
        __syncthreads();

        const __nv_bfloat16* Xhi_s = buf ? Xb1 : Xb0;
        const __nv_bfloat16* Xlo_s = Xhi_s + DD * XP;
        const __nv_bfloat16* Whi_s = Wp;
        const __nv_bfloat16* Wlo_s = Wp + DD * XP;

        float acc[4][4][4];
#pragma unroll
        for (int mt = 0; mt < 4; mt++)
#pragma unroll
            for (int nt = 0; nt < 4; nt++)
#pragma unroll
                for (int q = 0; q < 4; q++) acc[mt][nt][q] = 0.f;

        const int arow = wm * 64 + g;
        const int bcol = wn * 32 + g;

#pragma unroll
        for (int ks = 0; ks < 8; ks++) {
            const int k0 = ks * 16 + 2 * tg;
            unsigned ah[4][4], bh[4][2];
#pragma unroll
            for (int mt = 0; mt < 4; mt++) {
                const __nv_bfloat16* pa = Xhi_s + (arow + mt * 16) * XP + k0;
                ah[mt][0] = *(const unsigned*)pa;
                ah[mt][1] = *(const unsigned*)(pa + 8 * XP);
                ah[mt][2] = *(const unsigned*)(pa + 8);
                ah[mt][3] = *(const unsigned*)(pa + 8 * XP + 8);
            }
#pragma unroll
            for (int nt = 0; nt < 4; nt++) {
                const __nv_bfloat16* pb = Whi_s + (bcol + nt * 8) * XP + k0;
                bh[nt][0] = *(const unsigned*)pb;
                bh[nt][1] = *(const unsigned*)(pb + 8);
            }
#pragma unroll
            for (int mt = 0; mt < 4; mt++)
#pragma unroll
                for (int nt = 0; nt < 4; nt++) mma16816(acc[mt][nt], ah[mt], bh[nt]);
            {
                unsigned al[4][4];
#pragma unroll
                for (int mt = 0; mt < 4; mt++) {
                    const __nv_bfloat16* pa = Xlo_s + (arow + mt * 16) * XP + k0;
                    al[mt][0] = *(const unsigned*)pa;
                    al[mt][1] = *(const unsigned*)(pa + 8 * XP);
                    al[mt][2] = *(const unsigned*)(pa + 8);
                    al[mt][3] = *(const unsigned*)(pa + 8 * XP + 8);
                }
#pragma unroll
                for (int mt = 0; mt < 4; mt++)
#pragma unroll
                    for (int nt = 0; nt < 4; nt++) mma16816(acc[mt][nt], al[mt], bh[nt]);
            }
            {
                unsigned bl[4][2];
#pragma unroll
                for (int nt = 0; nt < 4; nt++) {
                    const __nv_bfloat16* pb = Wlo_s + (bcol + nt * 8) * XP + k0;
                    bl[nt][0] = *(const unsigned*)pb;
                    bl[nt][1] = *(const unsigned*)(pb + 8);
                }
#pragma unroll
                for (int mt = 0; mt < 4; mt++)
#pragma unroll
                    for (int nt = 0; nt < 4; nt++) mma16816(acc[mt][nt], ah[mt], bl[nt]);
            }
        }

        const size_t rbase = (size_t)c * 128;
#pragma unroll
        for (int mt = 0; mt < 4; mt++) {
#pragma unroll
            for (int nt = 0; nt < 4; nt++) {
                size_t r1 = rbase + wm * 64 + mt * 16 + g;
                int col = gate * 128 + wn * 32 + nt * 8 + 2 * tg;
                *(float2*)&g_Ax[r1 * NN + col] = make_float2(acc[mt][nt][0], acc[mt][nt][1]);
                *(float2*)&g_Ax[(r1 + 8) * NN + col] = make_float2(acc[mt][nt][2], acc[mt][nt][3]);
            }
        }
        __syncthreads();
        buf ^= 1;
    }
}

// ==================== phase 2: recurrence, operand-swapped mma ====================
// A = Wb^T (M=384, 24 m16-tiles), B = state (N=8, no padding). 12 warps, 2 tiles each.
// W_hi fragments in registers (step-invariant); W_lo in smem; state hi/lo in smem.
// pre2[n][batch] f32 results; canonical fp32 state sf.
#define OFF_SA2  98304                 // after W_lo [384*64 words]
#define OFF_SF2  106496                // after sA [2*8*64 words]
#define OFF_PRE2 110720                // after sf [8*132 floats]
#define RC_SMEM  126080                // + pre2 [384*10 floats]

__global__ __launch_bounds__(384, 1)
void recur_tc(const float* __restrict__ state0,
              const float* __restrict__ att,    // [T,B,1]
              const float* __restrict__ mask,   // [B,T]
              const float* __restrict__ bau, const float* __restrict__ bar,
              const float* __restrict__ bac,
              const float* __restrict__ Wbu, const float* __restrict__ Wbr,
              const float* __restrict__ Wbc,
              float* __restrict__ out) {
    extern __shared__ char sm[];
    unsigned* WloS = (unsigned*)sm;               // [384 n][64 words] rotated
    unsigned* sA   = (unsigned*)(sm + OFF_SA2);   // [split][8 rows][64 words] rotated
    float* sf   = (float*)(sm + OFF_SF2);         // [8][132] canonical fp32 state
    float* pre2 = (float*)(sm + OFF_PRE2);        // [384 n][10] matvec results [n][batch]

    const int tid = threadIdx.x;
    const int lane = tid & 31, wid = tid >> 5;
    const int b0 = blockIdx.x * 8;
    const int d = tid & 127;
    const int ar = lane >> 2;            // 0..7
    const int q2 = (lane & 3) * 2;
    const int nb0 = 32 * wid;            // warp's global n base (2 tiles: nb0, nb0+16)

    // ---- W_lo -> smem (rotated interleaved) ----
#pragma unroll 4
    for (int i = 0; i < 128; i++) {
        int idx = i * 384 + tid;         // 0..49151
        int g = idx >> 14;
        int k = (idx >> 7) & 127;
        int dd = idx & 127;
        const float* Wg = (g == 0) ? Wbu : ((g == 1) ? Wbr : Wbc);
        float v = Wg[k * DD + dd];
        __nv_bfloat16 h = __float2bfloat16(v);
        __nv_bfloat16 l = __float2bfloat16(v - __bfloat162float(h));
        int n = g * 128 + dd;
        int pos = n * 64 + ((word_of(k) + 8 * (n & 7)) & 63);
        ((__nv_bfloat16*)WloS)[pos * 2 + (k & 1)] = l;
    }

    // ---- W_hi fragments -> registers (per-lane direct LDG; one-time) ----
    const float* Wg = (wid < 4) ? Wbu : ((wid < 8) ? Wbr : Wbc);
    const int ddb = (wid & 3) * 32 + ar;     // within-gate d for tile0 row ar
    unsigned whi0[8][4], whi1[8][4];
#pragma unroll
    for (int ks = 0; ks < 8; ks++) {
        const int k0 = ks * 16 + q2;
#pragma unroll
        for (int jj = 0; jj < 4; jj++) {
            int kk = k0 + (jj >> 1) * 8;            // a0,a1: k0 ; a2,a3: k0+8
            int dj = ddb + (jj & 1) * 8;            // a0,a2: row ar ; a1,a3: row ar+8
            whi0[ks][jj] = pack2bf(__float2bfloat16(Wg[kk * DD + dj]),
                                   __float2bfloat16(Wg[(kk + 1) * DD + dj]));
            whi1[ks][jj] = pack2bf(__float2bfloat16(Wg[kk * DD + dj + 16]),
                                   __float2bfloat16(Wg[(kk + 1) * DD + dj + 16]));
        }
    }

    // ---- init state (fp32 canonical + hi/lo rotated splits) ----
    float bu = bau[d], brg = bar[d], bcg = bac[d];
#pragma unroll
    for (int ii = 0; ii < 3; ii++) {
        int i = tid + ii * 384;
        if (i < 1024) {
            int r = i >> 7, dd = i & 127;
            float v = state0[(size_t)(b0 + r) * DD + dd];
            sf[r * 132 + dd] = v;
            __nv_bfloat16 h = __float2bfloat16(v);
            __nv_bfloat16 l = __float2bfloat16(v - __bfloat162float(h));
            int pos = r * 64 + ((word_of(dd) + 8 * r) & 63);
            ((__nv_bfloat16*)sA)[pos * 2 + (dd & 1)] = h;
            ((__nv_bfloat16*)sA)[1024 + pos * 2 + (dd & 1)] = l;
        }
    }
    __syncthreads();

    for (int t = 0; t < TT; t++) {
        // early LDG: this step's x-projections + att/mask (hidden under matvec)
        float axu[3], axr[3], axc[3], av[3], mv[3];
#pragma unroll
        for (int ii = 0; ii < 3; ii++) {
            int i = tid + ii * 384;
            if (i < 1024) {
                int r = i >> 7;
                size_t row = (size_t)t * BB + b0 + r;
                axu[ii] = g_Ax[row * NN + d];
                axr[ii] = g_Ax[row * NN + 128 + d];
                axc[ii] = g_Ax[row * NN + 256 + d];
                av[ii] = att[t * BB + b0 + r];
                mv[ii] = mask[(size_t)(b0 + r) * TT + t];
            }
        }

        // ---- matvec: Wb^T @ s^T  (A = weights, B = state) ----
        float accA0[4], accB0[4], accA1[4], accB1[4];
#pragma unroll
        for (int q = 0; q < 4; q++) {
            accA0[q] = 0.f; accB0[q] = 0.f; accA1[q] = 0.f; accB1[q] = 0.f;
        }

#pragma unroll
        for (int ks = 0; ks < 8; ks++) {
            const int rot = (ks * 8 + q2 + 8 * ar) & 63;
            // state fragments (shared by both tiles)
            uint2 BH = *(const uint2*)(sA + ar * 64 + rot);
            uint2 BL = *(const uint2*)(sA + 512 + ar * 64 + rot);
            unsigned bh[2] = {BH.x, BH.y};
            unsigned bl[2] = {BL.x, BL.y};
            // W_lo fragments from smem
            uint2 L0a = *(const uint2*)(WloS + (nb0 + ar) * 64 + rot);
            uint2 L0b = *(const uint2*)(WloS + (nb0 + ar + 8) * 64 + rot);
            uint2 L1a = *(const uint2*)(WloS + (nb0 + 16 + ar) * 64 + rot);
            uint2 L1b = *(const uint2*)(WloS + (nb0 + 24 + ar) * 64 + rot);
            unsigned al0[4] = {L0a.x, L0b.x, L0a.y, L0b.y};
            unsigned al1[4] = {L1a.x, L1b.x, L1a.y, L1b.y};

            mma16816(accA0, whi0[ks], bh);
            mma16816(accB0, al0, bh);
            mma16816(accB0, whi0[ks], bl);
            mma16816(accA1, whi1[ks], bh);
            mma16816(accB1, al1, bh);
            mma16816(accB1, whi1[ks], bl);
        }

        // D: rows = weight n (nb0+ar, +8 / +16, +24), cols = batch (q2, q2+1)
        *(float2*)(pre2 + (nb0 + ar) * 10 + q2) =
            make_float2(accA0[0] + accB0[0], accA0[1] + accB0[1]);
        *(float2*)(pre2 + (nb0 + ar + 8) * 10 + q2) =
            make_float2(accA0[2] + accB0[2], accA0[3] + accB0[3]);
        *(float2*)(pre2 + (nb0 + 16 + ar) * 10 + q2) =
            make_float2(accA1[0] + accB1[0], accA1[1] + accB1[1]);
        *(float2*)(pre2 + (nb0 + 24 + ar) * 10 + q2) =
            make_float2(accA1[2] + accB1[2], accA1[3] + accB1[3]);
        __syncthreads();   // B1: pre2 visible; sA reads done

        // ---- gates + state update (items tid, tid+384, tid+768) ----
#pragma unroll
        for (int ii = 0; ii < 3; ii++) {
            int i = tid + ii * 384;
            if (i < 1024) {
                int r = i >> 7;
                float pu = pre2[d * 10 + r];
                float pr = pre2[(128 + d) * 10 + r];
                float pc = pre2[(256 + d) * 10 + r];
                float u = fsig(axu[ii] + bu + pu);
                float rg = fsig(axr[ii] + brg + pr);
                float c = ftanh(axc[ii] + bcg + rg * pc);
                float so = sf[r * 132 + d];
                float sn = so + mv[ii] * (av[ii] * u * (c - so));
                sf[r * 132 + d] = sn;
                __nv_bfloat16 h = __float2bfloat16(sn);
                __nv_bfloat16 l = __float2bfloat16(sn - __bfloat162float(h));
                int pos = r * 64 + ((word_of(d) + 8 * r) & 63);
                ((__nv_bfloat16*)sA)[pos * 2 + (d & 1)] = h;
                ((__nv_bfloat16*)sA)[1024 + pos * 2 + (d & 1)] = l;
            }
        }
        __syncthreads();   // B2: new state visible for next matvec
    }

#pragma unroll
    for (int ii = 0; ii < 3; ii++) {
        int i = tid + ii * 384;
        if (i < 1024) {
            int r = i >> 7;
            out[(size_t)(b0 + r) * DD + d] = sf[r * 132 + d];
        }
    }
}

// ---------------- launch ----------------
extern "C" void kernel_launch(void* const* d_in, const int* in_sizes, int n_in,
                              void* d_out, int out_size) {
    const float* inputs = (const float*)d_in[0];   // [T,B,D]
    const float* state  = (const float*)d_in[1];   // [B,D]
    const float* att    = (const float*)d_in[2];   // [T,B,1]
    const float* mask   = (const float*)d_in[3];   // [B,T]
    // d_in[4] = max_len (compile-time TT)
    const float* Wau = (const float*)d_in[5];
    const float* bau = (const float*)d_in[6];
    const float* Wbu = (const float*)d_in[7];
    const float* War = (const float*)d_in[8];
    const float* bar = (const float*)d_in[9];
    const float* Wbr = (const float*)d_in[10];
    const float* Wac = (const float*)d_in[11];
    const float* bac = (const float*)d_in[12];
    const float* Wbc = (const float*)d_in[13];

    cudaFuncSetAttribute(xproj_tc, cudaFuncAttributeMaxDynamicSharedMemorySize, XTC_SMEM);
    cudaFuncSetAttribute(recur_tc, cudaFuncAttributeMaxDynamicSharedMemorySize, RC_SMEM);

    prep_w<<<3, 256>>>(Wau, War, Wac);
    prep_x<<<2048, 256>>>((const float4*)inputs);
    xproj_tc<<<3 * GCH, 256, XTC_SMEM>>>();
    recur_tc<<<BB / 8, 384, RC_SMEM>>>(state, att, mask, bau, bar, bac,
                                       Wbu, Wbr, Wbc, (float*)d_out);
}